// round 8
// baseline (speedup 1.0000x reference)
#include <cuda_runtime.h>
#include <cuda_bf16.h>
#include <math.h>
#include <stdint.h>

#define N_NODES 100000
#define N_EDGES 1000000
#define FEAT 64
#define N_GRAPHS 512
#define N_CLS 10
#define BN_EPS 1e-5f
#define CAP 96

// Scratch (device globals — no allocation allowed)
__device__ float g_t[N_NODES * FEAT];      // pull-gather output (t = x + agg)
__device__ float g_h1[N_NODES * FEAT];
__device__ float g_sums[N_GRAPHS * FEAT];
__device__ float g_cnts[N_GRAPHS];
__device__ int   g_deg[N_NODES];
__device__ int   g_csr[N_NODES * CAP];

// ---------------------------------------------------------------------------
// helpers
// ---------------------------------------------------------------------------
__device__ __forceinline__ uint32_t f2tf32(float x) {
    uint32_t r;
    asm("cvt.rna.tf32.f32 %0, %1;" : "=r"(r) : "f"(x));
    return r;
}

__device__ __forceinline__ void mma_tf32(float* c, const uint32_t* a,
                                         uint32_t b0, uint32_t b1) {
    asm("mma.sync.aligned.m16n8k8.row.col.f32.tf32.tf32.f32 "
        "{%0,%1,%2,%3}, {%4,%5,%6,%7}, {%8,%9}, {%0,%1,%2,%3};"
        : "+f"(c[0]), "+f"(c[1]), "+f"(c[2]), "+f"(c[3])
        : "r"(a[0]), "r"(a[1]), "r"(a[2]), "r"(a[3]), "r"(b0), "r"(b1));
}

// SMEM layout (bytes)
#define A_STRIDE 68
#define W_STRIDE 72
#define SM_A   0
#define SM_W1  34816
#define SM_W2  (SM_W1 + 18432)
#define SM_B0  (SM_W2 + 18432)
#define SM_B1  (SM_B0 + 256)
#define SM_SS  (SM_B1 + 256)
#define SM_BAT (SM_SS + 256)
#define SM_TOTAL (SM_BAT + 512)

// ---------------------------------------------------------------------------
// CSR fill: csr[dst*CAP + pos] = src
// ---------------------------------------------------------------------------
__global__ __launch_bounds__(256) void fill_kernel(
    const int* __restrict__ src, const int* __restrict__ dst,
    int* __restrict__ deg, int* __restrict__ csr)
{
    int e = blockIdx.x * blockDim.x + threadIdx.x;
    if (e >= N_EDGES) return;
    int d = __ldg(dst + e);
    int pos = atomicAdd(deg + d, 1);
    if (pos < CAP) csr[d * CAP + pos] = __ldg(src + e);
}

// ---------------------------------------------------------------------------
// Pull gather: t[node] = h[node] + sum_{j in csr[node]} h[j]
// ---------------------------------------------------------------------------
__global__ __launch_bounds__(256) void gather_kernel(
    const float* __restrict__ h,
    const int* __restrict__ deg, const int* __restrict__ csr,
    float* __restrict__ tout)
{
    long long tid = (long long)blockIdx.x * blockDim.x + threadIdx.x;
    int node = (int)(tid >> 4);
    int c = (int)(tid & 15);
    if (node >= N_NODES) return;

    int dg = __ldg(deg + node);
    if (dg > CAP) dg = CAP;
    const int* lst = csr + (size_t)node * CAP;

    float4 acc = __ldg(reinterpret_cast<const float4*>(h + (size_t)node * FEAT) + c);

    int i = 0;
    for (; i + 4 <= dg; i += 4) {
        int s0 = __ldg(lst + i);
        int s1 = __ldg(lst + i + 1);
        int s2 = __ldg(lst + i + 2);
        int s3 = __ldg(lst + i + 3);
        float4 a = __ldg(reinterpret_cast<const float4*>(h + (size_t)s0 * FEAT) + c);
        float4 b = __ldg(reinterpret_cast<const float4*>(h + (size_t)s1 * FEAT) + c);
        float4 d = __ldg(reinterpret_cast<const float4*>(h + (size_t)s2 * FEAT) + c);
        float4 e = __ldg(reinterpret_cast<const float4*>(h + (size_t)s3 * FEAT) + c);
        acc.x += a.x; acc.y += a.y; acc.z += a.z; acc.w += a.w;
        acc.x += b.x; acc.y += b.y; acc.z += b.z; acc.w += b.w;
        acc.x += d.x; acc.y += d.y; acc.z += d.z; acc.w += d.w;
        acc.x += e.x; acc.y += e.y; acc.z += e.z; acc.w += e.w;
    }
    for (; i < dg; i++) {
        int s = __ldg(lst + i);
        float4 a = __ldg(reinterpret_cast<const float4*>(h + (size_t)s * FEAT) + c);
        acc.x += a.x; acc.y += a.y; acc.z += a.z; acc.w += a.w;
    }
    *(reinterpret_cast<float4*>(tout + (size_t)node * FEAT) + c) = acc;
}

// ---------------------------------------------------------------------------
__global__ __launch_bounds__(256) void count_kernel(
    const int* __restrict__ batch, float* __restrict__ cnts)
{
    int i = blockIdx.x * blockDim.x + threadIdx.x;
    if (i < N_NODES) atomicAdd(cnts + __ldg(batch + i), 1.0f);
}

// ---------------------------------------------------------------------------
// Fused GIN MLP on pre-aggregated t: 128-node tile, 8 warps (N split 32/warp).
// Warp w: rows (w&3)*32..+32, cols (w>>2)*32..+32.
// mode 0: out[node] = relu(mlp(t))
// mode 1: segmented block-reduce mlp(t) rows by sorted batch -> red to sums
// ---------------------------------------------------------------------------
__global__ __launch_bounds__(256, 3) void conv_kernel(
    const float* __restrict__ tin,
    const float* __restrict__ wa, const float* __restrict__ ba,
    const float* __restrict__ gam, const float* __restrict__ bet,
    const float* __restrict__ mu,  const float* __restrict__ var,
    const float* __restrict__ wb,  const float* __restrict__ bb,
    float* __restrict__ out, const int* __restrict__ batch,
    float* __restrict__ sums, int mode)
{
    extern __shared__ __align__(16) char sm[];
    float* A_s  = (float*)(sm + SM_A);
    float* W1_s = (float*)(sm + SM_W1);
    float* W2_s = (float*)(sm + SM_W2);
    float* b0_s = (float*)(sm + SM_B0);
    float* b1_s = (float*)(sm + SM_B1);
    float* s_s  = (float*)(sm + SM_SS);
    int*   bat_s = (int*)(sm + SM_BAT);

    int tid = threadIdx.x;
    int wid = tid >> 5;
    int lane = tid & 31;
    int g = lane >> 2;   // group id (0..7)
    int t = lane & 3;    // thread-in-group (0..3)
    int mw = wid & 3;    // row group of warp (32 rows)
    int nw = wid >> 1 & 2;  // 0 or 2 -> col base = nw*16... (computed below)
    int ncol0 = (wid >> 2) * 32;   // column base for this warp

    if (tid < FEAT) {
        float s = gam[tid] * rsqrtf(var[tid] + BN_EPS);
        s_s[tid] = s;
        b0_s[tid] = (ba[tid] - mu[tid]) * s + bet[tid];
        b1_s[tid] = bb[tid];
    }
    __syncthreads();

    // stage weights (BN scale folded into W1), tf32-rounded
    for (int i = tid; i < FEAT * FEAT; i += 256) {
        int n = i & 63;
        W1_s[(i >> 6) * W_STRIDE + n] = __uint_as_float(f2tf32(wa[i] * s_s[n]));
        W2_s[(i >> 6) * W_STRIDE + n] = __uint_as_float(f2tf32(wb[i]));
    }

    // stage A = tf32(t): 2 threads per row (each stages 32 floats)
    int node_base = blockIdx.x * 128;
    {
        int row = tid >> 1;
        int half = tid & 1;
        int node = node_base + row;
        float* arow = A_s + row * A_STRIDE + half * 32;
        if (node < N_NODES) {
            const float4* tp = (const float4*)(tin + (size_t)node * FEAT) + half * 8;
#pragma unroll
            for (int q = 0; q < 8; q++) {
                float4 a = __ldg(tp + q);
                arow[4 * q + 0] = __uint_as_float(f2tf32(a.x));
                arow[4 * q + 1] = __uint_as_float(f2tf32(a.y));
                arow[4 * q + 2] = __uint_as_float(f2tf32(a.z));
                arow[4 * q + 3] = __uint_as_float(f2tf32(a.w));
            }
        } else {
#pragma unroll
            for (int q = 0; q < 8; q++) {
                arow[4 * q + 0] = 0.0f; arow[4 * q + 1] = 0.0f;
                arow[4 * q + 2] = 0.0f; arow[4 * q + 3] = 0.0f;
            }
        }
        if (half == 0) bat_s[row] = (node < N_NODES) ? __ldg(batch + row + node_base) : -1;
    }
    __syncthreads();

    const float* Aw = A_s + (mw * 32) * A_STRIDE;
    float* Aww = A_s + (mw * 32) * A_STRIDE;

    float acc[2][4][4];

#define GEMM_LAYER(WS)                                                        \
    {                                                                         \
        _Pragma("unroll")                                                     \
        for (int mt = 0; mt < 2; mt++)                                        \
            _Pragma("unroll")                                                 \
            for (int nt = 0; nt < 4; nt++)                                    \
                _Pragma("unroll")                                             \
                for (int e = 0; e < 4; e++) acc[mt][nt][e] = 0.0f;            \
        _Pragma("unroll")                                                     \
        for (int ks = 0; ks < 8; ks++) {                                      \
            uint32_t af[2][4];                                                \
            _Pragma("unroll")                                                 \
            for (int mt = 0; mt < 2; mt++) {                                  \
                const float* ap = Aw + (mt * 16 + g) * A_STRIDE + ks * 8 + t; \
                af[mt][0] = __float_as_uint(ap[0]);                           \
                af[mt][1] = __float_as_uint(ap[8 * A_STRIDE]);                \
                af[mt][2] = __float_as_uint(ap[4]);                           \
                af[mt][3] = __float_as_uint(ap[8 * A_STRIDE + 4]);            \
            }                                                                 \
            _Pragma("unroll")                                                 \
            for (int nt = 0; nt < 4; nt++) {                                  \
                int col = ncol0 + nt * 8 + g;                                 \
                uint32_t b0 = __float_as_uint(WS[(ks * 8 + t) * W_STRIDE + col]);     \
                uint32_t b1 = __float_as_uint(WS[(ks * 8 + t + 4) * W_STRIDE + col]); \
                mma_tf32(acc[0][nt], af[0], b0, b1);                          \
                mma_tf32(acc[1][nt], af[1], b0, b1);                          \
            }                                                                 \
        }                                                                     \
    }

    // ---- Layer 1 ----
    GEMM_LAYER(W1_s);
    __syncthreads();   // all warps done reading A1

    // bias + relu, tf32-round, write u in place
#pragma unroll
    for (int mt = 0; mt < 2; mt++) {
#pragma unroll
        for (int nt = 0; nt < 4; nt++) {
            int col = ncol0 + nt * 8 + 2 * t;
            float bc0 = b0_s[col], bc1 = b0_s[col + 1];
            float v0 = fmaxf(acc[mt][nt][0] + bc0, 0.0f);
            float v1 = fmaxf(acc[mt][nt][1] + bc1, 0.0f);
            float v2 = fmaxf(acc[mt][nt][2] + bc0, 0.0f);
            float v3 = fmaxf(acc[mt][nt][3] + bc1, 0.0f);
            float* r0 = Aww + (mt * 16 + g) * A_STRIDE + col;
            float* r1 = Aww + (mt * 16 + g + 8) * A_STRIDE + col;
            r0[0] = __uint_as_float(f2tf32(v0));
            r0[1] = __uint_as_float(f2tf32(v1));
            r1[0] = __uint_as_float(f2tf32(v2));
            r1[1] = __uint_as_float(f2tf32(v3));
        }
    }
    __syncthreads();   // u complete

    // ---- Layer 2 ----
    GEMM_LAYER(W2_s);

    // ---- epilogue ----
    if (mode == 0) {
#pragma unroll
        for (int mt = 0; mt < 2; mt++) {
            int node0 = node_base + mw * 32 + mt * 16 + g;
            int node1 = node0 + 8;
#pragma unroll
            for (int nt = 0; nt < 4; nt++) {
                int col = ncol0 + nt * 8 + 2 * t;
                float bc0 = b1_s[col], bc1 = b1_s[col + 1];
                if (node0 < N_NODES) {
                    float2 v = make_float2(fmaxf(acc[mt][nt][0] + bc0, 0.0f),
                                           fmaxf(acc[mt][nt][1] + bc1, 0.0f));
                    *(float2*)(out + (size_t)node0 * FEAT + col) = v;
                }
                if (node1 < N_NODES) {
                    float2 v = make_float2(fmaxf(acc[mt][nt][2] + bc0, 0.0f),
                                           fmaxf(acc[mt][nt][3] + bc1, 0.0f));
                    *(float2*)(out + (size_t)node1 * FEAT + col) = v;
                }
            }
        }
    } else {
        __syncthreads();   // all warps done reading A (layer 2)
#pragma unroll
        for (int mt = 0; mt < 2; mt++) {
#pragma unroll
            for (int nt = 0; nt < 4; nt++) {
                int col = ncol0 + nt * 8 + 2 * t;
                float bc0 = b1_s[col], bc1 = b1_s[col + 1];
                float* r0 = Aww + (mt * 16 + g) * A_STRIDE + col;
                float* r1 = Aww + (mt * 16 + g + 8) * A_STRIDE + col;
                r0[0] = acc[mt][nt][0] + bc0;
                r0[1] = acc[mt][nt][1] + bc1;
                r1[0] = acc[mt][nt][2] + bc0;
                r1[1] = acc[mt][nt][3] + bc1;
            }
        }
        __syncthreads();

        // segmented column reduction over sorted batch ids
        int col = tid & 63;
        int quarter = tid >> 6;   // 0..3, 32 rows each
        int cur = -1;
        float run = 0.0f;
#pragma unroll 8
        for (int r = 0; r < 32; r++) {
            int rr = quarter * 32 + r;
            int b = bat_s[rr];
            float v = A_s[rr * A_STRIDE + col];
            if (b != cur) {
                if (cur >= 0) {
                    float* q = sums + (size_t)cur * FEAT + col;
                    asm volatile("red.global.add.f32 [%0], %1;"
                                 :: "l"(q), "f"(run) : "memory");
                }
                cur = b;
                run = 0.0f;
            }
            run += v;
        }
        if (cur >= 0) {
            float* q = sums + (size_t)cur * FEAT + col;
            asm volatile("red.global.add.f32 [%0], %1;"
                         :: "l"(q), "f"(run) : "memory");
        }
    }
#undef GEMM_LAYER
}

// ---------------------------------------------------------------------------
__global__ __launch_bounds__(64) void classify_kernel(
    const float* __restrict__ sums,
    const float* __restrict__ cnts,
    const float* __restrict__ wc,
    const float* __restrict__ bc,
    float* __restrict__ out)
{
    int g = blockIdx.x;
    int tid = threadIdx.x;
    __shared__ float p[FEAT];
    float cnt = fmaxf(__ldg(cnts + g), 1.0f);
    p[tid] = sums[(size_t)g * FEAT + tid] / cnt;
    __syncthreads();
    if (tid < N_CLS) {
        float acc = bc[tid];
#pragma unroll
        for (int k = 0; k < FEAT; k++) {
            acc = fmaf(p[k], wc[k * N_CLS + tid], acc);
        }
        out[(size_t)g * N_CLS + tid] = acc;
    }
}

// ---------------------------------------------------------------------------
extern "C" void kernel_launch(void* const* d_in, const int* in_sizes, int n_in,
                              void* d_out, int out_size)
{
    const float* x   = (const float*)d_in[0];
    const int*   ei  = (const int*)d_in[1];
    const int*   bat = (const int*)d_in[2];
    const float* w0a = (const float*)d_in[3];
    const float* b0a = (const float*)d_in[4];
    const float* g0  = (const float*)d_in[5];
    const float* be0 = (const float*)d_in[6];
    const float* m0  = (const float*)d_in[7];
    const float* v0  = (const float*)d_in[8];
    const float* w0b = (const float*)d_in[9];
    const float* b0b = (const float*)d_in[10];
    const float* w1a = (const float*)d_in[11];
    const float* b1a = (const float*)d_in[12];
    const float* g1  = (const float*)d_in[13];
    const float* be1 = (const float*)d_in[14];
    const float* m1  = (const float*)d_in[15];
    const float* v1  = (const float*)d_in[16];
    const float* w1b = (const float*)d_in[17];
    const float* b1b = (const float*)d_in[18];
    const float* wc  = (const float*)d_in[19];
    const float* bc  = (const float*)d_in[20];
    float* out = (float*)d_out;

    const int* src = ei;            // edge_index[0]
    const int* dst = ei + N_EDGES;  // edge_index[1]

    float *p_t, *p_h1, *p_sums, *p_cnts;
    int *p_deg, *p_csr;
    cudaGetSymbolAddress((void**)&p_t,    g_t);
    cudaGetSymbolAddress((void**)&p_h1,   g_h1);
    cudaGetSymbolAddress((void**)&p_sums, g_sums);
    cudaGetSymbolAddress((void**)&p_cnts, g_cnts);
    cudaGetSymbolAddress((void**)&p_deg,  g_deg);
    cudaGetSymbolAddress((void**)&p_csr,  g_csr);

    static bool attr_done = false;
    if (!attr_done) {
        cudaFuncSetAttribute(conv_kernel,
                             cudaFuncAttributeMaxDynamicSharedMemorySize,
                             SM_TOTAL);
        attr_done = true;
    }

    const int fill_blocks = (N_EDGES + 255) / 256;          // 3907
    const int gather_blocks = (N_NODES * 16 + 255) / 256;   // 6250
    const int conv_blocks = (N_NODES + 127) / 128;          // 782
    const int node_blocks = (N_NODES + 255) / 256;          // 391

    // ---- CSR build (shared by both convs) ----
    cudaMemsetAsync(p_deg, 0, (size_t)N_NODES * sizeof(int));
    cudaMemsetAsync(p_sums, 0, (size_t)N_GRAPHS * FEAT * sizeof(float));
    cudaMemsetAsync(p_cnts, 0, (size_t)N_GRAPHS * sizeof(float));
    fill_kernel<<<fill_blocks, 256>>>(src, dst, p_deg, p_csr);
    count_kernel<<<node_blocks, 256>>>(bat, p_cnts);

    // ---- Conv 0 ----
    gather_kernel<<<gather_blocks, 256>>>(x, p_deg, p_csr, p_t);
    conv_kernel<<<conv_blocks, 256, SM_TOTAL>>>(
        p_t, w0a, b0a, g0, be0, m0, v0,
        w0b, b0b, p_h1, bat, p_sums, /*mode=*/0);

    // ---- Conv 1 (mean-pool sum fused, segmented reduction) ----
    gather_kernel<<<gather_blocks, 256>>>(p_h1, p_deg, p_csr, p_t);
    conv_kernel<<<conv_blocks, 256, SM_TOTAL>>>(
        p_t, w1a, b1a, g1, be1, m1, v1,
        w1b, b1b, /*out unused*/ p_h1, bat, p_sums, /*mode=*/1);

    // ---- Classify ----
    classify_kernel<<<N_GRAPHS, 64>>>(p_sums, p_cnts, wc, bc, out);
}

// round 9
// speedup vs baseline: 1.0644x; 1.0644x over previous
#include <cuda_runtime.h>
#include <cuda_bf16.h>
#include <math.h>
#include <stdint.h>

#define N_NODES 100000
#define N_EDGES 1000000
#define FEAT 64
#define N_GRAPHS 512
#define N_CLS 10
#define BN_EPS 1e-5f
#define CAP 96

#define NTILES 782
#define GRID_CONV 261

// Scratch (device globals — no allocation allowed)
__device__ float g_t[N_NODES * FEAT];      // pull-gather output (t = x + agg)
__device__ float g_h1[N_NODES * FEAT];
__device__ float g_sums[N_GRAPHS * FEAT];
__device__ float g_cnts[N_GRAPHS];
__device__ int   g_deg[N_NODES];
__device__ int   g_csr[N_NODES * CAP];

// ---------------------------------------------------------------------------
// helpers
// ---------------------------------------------------------------------------
__device__ __forceinline__ uint32_t f2tf32(float x) {
    uint32_t r;
    asm("cvt.rna.tf32.f32 %0, %1;" : "=r"(r) : "f"(x));
    return r;
}

__device__ __forceinline__ void mma_tf32(float* c, const uint32_t* a,
                                         uint32_t b0, uint32_t b1) {
    asm("mma.sync.aligned.m16n8k8.row.col.f32.tf32.tf32.f32 "
        "{%0,%1,%2,%3}, {%4,%5,%6,%7}, {%8,%9}, {%0,%1,%2,%3};"
        : "+f"(c[0]), "+f"(c[1]), "+f"(c[2]), "+f"(c[3])
        : "r"(a[0]), "r"(a[1]), "r"(a[2]), "r"(a[3]), "r"(b0), "r"(b1));
}

// SMEM layout (bytes)
#define A_STRIDE 68
#define W_STRIDE 72
#define ABYTES   34816                      // 128 * 68 * 4
#define SM_A     0
#define SM_W1    69632                      // 2 * ABYTES
#define SM_W2    (SM_W1 + 18432)
#define SM_B0    (SM_W2 + 18432)
#define SM_B1    (SM_B0 + 256)
#define SM_BAT   (SM_B1 + 256)
#define SM_TOTAL (SM_BAT + 1024)            // 2 * 512B bat buffers

// ---------------------------------------------------------------------------
// CSR fill: csr[dst*CAP + pos] = src
// ---------------------------------------------------------------------------
__global__ __launch_bounds__(256) void fill_kernel(
    const int* __restrict__ src, const int* __restrict__ dst,
    int* __restrict__ deg, int* __restrict__ csr)
{
    int e = blockIdx.x * blockDim.x + threadIdx.x;
    if (e >= N_EDGES) return;
    int d = __ldg(dst + e);
    int pos = atomicAdd(deg + d, 1);
    if (pos < CAP) csr[d * CAP + pos] = __ldg(src + e);
}

// ---------------------------------------------------------------------------
// Pull gather: t[node] = h[node] + sum_{j in csr[node]} h[j]
// ---------------------------------------------------------------------------
__global__ __launch_bounds__(256) void gather_kernel(
    const float* __restrict__ h,
    const int* __restrict__ deg, const int* __restrict__ csr,
    float* __restrict__ tout)
{
    long long tid = (long long)blockIdx.x * blockDim.x + threadIdx.x;
    int node = (int)(tid >> 4);
    int c = (int)(tid & 15);
    if (node >= N_NODES) return;

    int dg = __ldg(deg + node);
    if (dg > CAP) dg = CAP;
    const int* lst = csr + (size_t)node * CAP;

    float4 acc = __ldg(reinterpret_cast<const float4*>(h + (size_t)node * FEAT) + c);

    int i = 0;
    for (; i + 4 <= dg; i += 4) {
        int s0 = __ldg(lst + i);
        int s1 = __ldg(lst + i + 1);
        int s2 = __ldg(lst + i + 2);
        int s3 = __ldg(lst + i + 3);
        float4 a = __ldg(reinterpret_cast<const float4*>(h + (size_t)s0 * FEAT) + c);
        float4 b = __ldg(reinterpret_cast<const float4*>(h + (size_t)s1 * FEAT) + c);
        float4 d = __ldg(reinterpret_cast<const float4*>(h + (size_t)s2 * FEAT) + c);
        float4 e = __ldg(reinterpret_cast<const float4*>(h + (size_t)s3 * FEAT) + c);
        acc.x += a.x; acc.y += a.y; acc.z += a.z; acc.w += a.w;
        acc.x += b.x; acc.y += b.y; acc.z += b.z; acc.w += b.w;
        acc.x += d.x; acc.y += d.y; acc.z += d.z; acc.w += d.w;
        acc.x += e.x; acc.y += e.y; acc.z += e.z; acc.w += e.w;
    }
    for (; i < dg; i++) {
        int s = __ldg(lst + i);
        float4 a = __ldg(reinterpret_cast<const float4*>(h + (size_t)s * FEAT) + c);
        acc.x += a.x; acc.y += a.y; acc.z += a.z; acc.w += a.w;
    }
    *(reinterpret_cast<float4*>(tout + (size_t)node * FEAT) + c) = acc;
}

// ---------------------------------------------------------------------------
__global__ __launch_bounds__(256) void count_kernel(
    const int* __restrict__ batch, float* __restrict__ cnts)
{
    int i = blockIdx.x * blockDim.x + threadIdx.x;
    if (i < N_NODES) atomicAdd(cnts + __ldg(batch + i), 1.0f);
}

// ---------------------------------------------------------------------------
// Stage one 128-node A tile (raw fp32) + batch ids into buffer `buf`
// via cp.async. Thread layout: 2 threads/row, 32 floats each.
// ---------------------------------------------------------------------------
__device__ __forceinline__ void stage_tile(char* sm, int buf,
                                           const float* __restrict__ tin,
                                           const int* __restrict__ batch,
                                           int tile)
{
    int tid = threadIdx.x;
    int row = tid >> 1, half = tid & 1;
    int node = tile * 128 + row;
    float* A_s = (float*)(sm + SM_A + buf * ABYTES);
    uint32_t dst = (uint32_t)__cvta_generic_to_shared(A_s + row * A_STRIDE + half * 32);
    if (node < N_NODES) {
        const float* src = tin + (size_t)node * FEAT + half * 32;
#pragma unroll
        for (int q = 0; q < 8; q++)
            asm volatile("cp.async.cg.shared.global [%0], [%1], 16;"
                         :: "r"(dst + q * 16), "l"(src + q * 4) : "memory");
    } else {
#pragma unroll
        for (int q = 0; q < 8; q++)
            asm volatile("st.shared.v4.b32 [%0], {%1,%1,%1,%1};"
                         :: "r"(dst + q * 16), "r"(0u) : "memory");
    }
    if (half == 0) {
        int* bat_s = (int*)(sm + SM_BAT + buf * 512);
        uint32_t bdst = (uint32_t)__cvta_generic_to_shared(bat_s + row);
        if (node < N_NODES)
            asm volatile("cp.async.ca.shared.global [%0], [%1], 4;"
                         :: "r"(bdst), "l"(batch + node) : "memory");
        else
            asm volatile("st.shared.b32 [%0], %1;"
                         :: "r"(bdst), "r"(0xFFFFFFFFu) : "memory");
    }
    asm volatile("cp.async.commit_group;" ::: "memory");
}

// ---------------------------------------------------------------------------
// Persistent fused GIN MLP: 261 blocks x 3 tiles, cp.async double buffering.
// 8 warps/block: warp w -> rows (w&3)*32, cols (w>>2)*32.
// mode 0: out[node] = relu(mlp(t))
// mode 1: segmented block-reduce mlp(t) rows by sorted batch -> red to sums
// ---------------------------------------------------------------------------
__global__ __launch_bounds__(256, 2) void conv_kernel(
    const float* __restrict__ tin,
    const float* __restrict__ wa, const float* __restrict__ ba,
    const float* __restrict__ gam, const float* __restrict__ bet,
    const float* __restrict__ mu,  const float* __restrict__ var,
    const float* __restrict__ wb,  const float* __restrict__ bb,
    float* __restrict__ out, const int* __restrict__ batch,
    float* __restrict__ sums, int mode)
{
    extern __shared__ __align__(16) char sm[];
    float* W1_s = (float*)(sm + SM_W1);
    float* W2_s = (float*)(sm + SM_W2);
    float* b0_s = (float*)(sm + SM_B0);
    float* b1_s = (float*)(sm + SM_B1);

    int tid = threadIdx.x;
    int wid = tid >> 5;
    int lane = tid & 31;
    int g = lane >> 2;
    int t = lane & 3;
    int mw = wid & 3;
    int ncol0 = (wid >> 2) * 32;

    // kick off the first tile's async stage immediately
    stage_tile(sm, 0, tin, batch, blockIdx.x);

    // stage weights once per block (BN folded into W1), tf32-rounded
    for (int i = tid; i < FEAT * FEAT; i += 256) {
        int n = i & 63;
        float s = __ldg(gam + n) * rsqrtf(__ldg(var + n) + BN_EPS);
        W1_s[(i >> 6) * W_STRIDE + n] = __uint_as_float(f2tf32(__ldg(wa + i) * s));
        W2_s[(i >> 6) * W_STRIDE + n] = __uint_as_float(f2tf32(__ldg(wb + i)));
    }
    if (tid < FEAT) {
        float s = __ldg(gam + tid) * rsqrtf(__ldg(var + tid) + BN_EPS);
        b0_s[tid] = (__ldg(ba + tid) - __ldg(mu + tid)) * s + __ldg(bet + tid);
        b1_s[tid] = __ldg(bb + tid);
    }

    int buf = 0;
    for (int tile = blockIdx.x; tile < NTILES; tile += GRID_CONV) {
        int nxt = tile + GRID_CONV;
        if (nxt < NTILES) {
            stage_tile(sm, buf ^ 1, tin, batch, nxt);
            asm volatile("cp.async.wait_group 1;" ::: "memory");
        } else {
            asm volatile("cp.async.wait_group 0;" ::: "memory");
        }
        __syncthreads();   // current buffer ready (weights too, first iter)

        float* A_s  = (float*)(sm + SM_A + buf * ABYTES);
        int* bat_s  = (int*)(sm + SM_BAT + buf * 512);
        const float* Aw = A_s + (mw * 32) * A_STRIDE;
        float* Aww = A_s + (mw * 32) * A_STRIDE;
        int node_base = tile * 128;

        float acc[2][4][4];

#define GEMM_LAYER(WS)                                                        \
    {                                                                         \
        _Pragma("unroll")                                                     \
        for (int mt = 0; mt < 2; mt++)                                        \
            _Pragma("unroll")                                                 \
            for (int nt = 0; nt < 4; nt++)                                    \
                _Pragma("unroll")                                             \
                for (int e = 0; e < 4; e++) acc[mt][nt][e] = 0.0f;            \
        _Pragma("unroll")                                                     \
        for (int ks = 0; ks < 8; ks++) {                                      \
            uint32_t af[2][4];                                                \
            _Pragma("unroll")                                                 \
            for (int mt = 0; mt < 2; mt++) {                                  \
                const float* ap = Aw + (mt * 16 + g) * A_STRIDE + ks * 8 + t; \
                af[mt][0] = f2tf32(ap[0]);                                    \
                af[mt][1] = f2tf32(ap[8 * A_STRIDE]);                         \
                af[mt][2] = f2tf32(ap[4]);                                    \
                af[mt][3] = f2tf32(ap[8 * A_STRIDE + 4]);                     \
            }                                                                 \
            _Pragma("unroll")                                                 \
            for (int nt = 0; nt < 4; nt++) {                                  \
                int col = ncol0 + nt * 8 + g;                                 \
                uint32_t b0 = __float_as_uint(WS[(ks * 8 + t) * W_STRIDE + col]);     \
                uint32_t b1 = __float_as_uint(WS[(ks * 8 + t + 4) * W_STRIDE + col]); \
                mma_tf32(acc[0][nt], af[0], b0, b1);                          \
                mma_tf32(acc[1][nt], af[1], b0, b1);                          \
            }                                                                 \
        }                                                                     \
    }

        // ---- Layer 1 ----
        GEMM_LAYER(W1_s);
        __syncthreads();   // all warps done reading A1

        // bias + relu, write u in place (raw float; layer-2 fragments re-cvt)
#pragma unroll
        for (int mt = 0; mt < 2; mt++) {
#pragma unroll
            for (int nt = 0; nt < 4; nt++) {
                int col = ncol0 + nt * 8 + 2 * t;
                float bc0 = b0_s[col], bc1 = b0_s[col + 1];
                float* r0 = Aww + (mt * 16 + g) * A_STRIDE + col;
                float* r1 = Aww + (mt * 16 + g + 8) * A_STRIDE + col;
                r0[0] = fmaxf(acc[mt][nt][0] + bc0, 0.0f);
                r0[1] = fmaxf(acc[mt][nt][1] + bc1, 0.0f);
                r1[0] = fmaxf(acc[mt][nt][2] + bc0, 0.0f);
                r1[1] = fmaxf(acc[mt][nt][3] + bc1, 0.0f);
            }
        }
        __syncthreads();   // u complete

        // ---- Layer 2 ----
        GEMM_LAYER(W2_s);

        // ---- epilogue ----
        if (mode == 0) {
#pragma unroll
            for (int mt = 0; mt < 2; mt++) {
                int node0 = node_base + mw * 32 + mt * 16 + g;
                int node1 = node0 + 8;
#pragma unroll
                for (int nt = 0; nt < 4; nt++) {
                    int col = ncol0 + nt * 8 + 2 * t;
                    float bc0 = b1_s[col], bc1 = b1_s[col + 1];
                    if (node0 < N_NODES) {
                        float2 v = make_float2(fmaxf(acc[0][nt][0] + bc0, 0.0f),
                                               fmaxf(acc[0][nt][1] + bc1, 0.0f));
                        if (mt == 1) v = make_float2(fmaxf(acc[1][nt][0] + bc0, 0.0f),
                                                     fmaxf(acc[1][nt][1] + bc1, 0.0f));
                        *(float2*)(out + (size_t)node0 * FEAT + col) = v;
                    }
                    if (node1 < N_NODES) {
                        float2 v = make_float2(fmaxf(acc[0][nt][2] + bc0, 0.0f),
                                               fmaxf(acc[0][nt][3] + bc1, 0.0f));
                        if (mt == 1) v = make_float2(fmaxf(acc[1][nt][2] + bc0, 0.0f),
                                                     fmaxf(acc[1][nt][3] + bc1, 0.0f));
                        *(float2*)(out + (size_t)node1 * FEAT + col) = v;
                    }
                }
            }
        } else {
            __syncthreads();   // all warps done reading A (layer 2)
#pragma unroll
            for (int mt = 0; mt < 2; mt++) {
#pragma unroll
                for (int nt = 0; nt < 4; nt++) {
                    int col = ncol0 + nt * 8 + 2 * t;
                    float bc0 = b1_s[col], bc1 = b1_s[col + 1];
                    float* r0 = Aww + (mt * 16 + g) * A_STRIDE + col;
                    float* r1 = Aww + (mt * 16 + g + 8) * A_STRIDE + col;
                    r0[0] = acc[mt][nt][0] + bc0;
                    r0[1] = acc[mt][nt][1] + bc1;
                    r1[0] = acc[mt][nt][2] + bc0;
                    r1[1] = acc[mt][nt][3] + bc1;
                }
            }
            __syncthreads();

            // segmented column reduction over sorted batch ids
            int col = tid & 63;
            int quarter = tid >> 6;
            int cur = -1;
            float run = 0.0f;
#pragma unroll 8
            for (int r = 0; r < 32; r++) {
                int rr = quarter * 32 + r;
                int b = bat_s[rr];
                float v = A_s[rr * A_STRIDE + col];
                if (b != cur) {
                    if (cur >= 0) {
                        float* q = sums + (size_t)cur * FEAT + col;
                        asm volatile("red.global.add.f32 [%0], %1;"
                                     :: "l"(q), "f"(run) : "memory");
                    }
                    cur = b;
                    run = 0.0f;
                }
                run += v;
            }
            if (cur >= 0) {
                float* q = sums + (size_t)cur * FEAT + col;
                asm volatile("red.global.add.f32 [%0], %1;"
                             :: "l"(q), "f"(run) : "memory");
            }
        }
        __syncthreads();   // done reading this buffer before it is re-staged
        buf ^= 1;
#undef GEMM_LAYER
    }
}

// ---------------------------------------------------------------------------
__global__ __launch_bounds__(64) void classify_kernel(
    const float* __restrict__ sums,
    const float* __restrict__ cnts,
    const float* __restrict__ wc,
    const float* __restrict__ bc,
    float* __restrict__ out)
{
    int g = blockIdx.x;
    int tid = threadIdx.x;
    __shared__ float p[FEAT];
    float cnt = fmaxf(__ldg(cnts + g), 1.0f);
    p[tid] = sums[(size_t)g * FEAT + tid] / cnt;
    __syncthreads();
    if (tid < N_CLS) {
        float acc = bc[tid];
#pragma unroll
        for (int k = 0; k < FEAT; k++) {
            acc = fmaf(p[k], wc[k * N_CLS + tid], acc);
        }
        out[(size_t)g * N_CLS + tid] = acc;
    }
}

// ---------------------------------------------------------------------------
extern "C" void kernel_launch(void* const* d_in, const int* in_sizes, int n_in,
                              void* d_out, int out_size)
{
    const float* x   = (const float*)d_in[0];
    const int*   ei  = (const int*)d_in[1];
    const int*   bat = (const int*)d_in[2];
    const float* w0a = (const float*)d_in[3];
    const float* b0a = (const float*)d_in[4];
    const float* g0  = (const float*)d_in[5];
    const float* be0 = (const float*)d_in[6];
    const float* m0  = (const float*)d_in[7];
    const float* v0  = (const float*)d_in[8];
    const float* w0b = (const float*)d_in[9];
    const float* b0b = (const float*)d_in[10];
    const float* w1a = (const float*)d_in[11];
    const float* b1a = (const float*)d_in[12];
    const float* g1  = (const float*)d_in[13];
    const float* be1 = (const float*)d_in[14];
    const float* m1  = (const float*)d_in[15];
    const float* v1  = (const float*)d_in[16];
    const float* w1b = (const float*)d_in[17];
    const float* b1b = (const float*)d_in[18];
    const float* wc  = (const float*)d_in[19];
    const float* bc  = (const float*)d_in[20];
    float* out = (float*)d_out;

    const int* src = ei;            // edge_index[0]
    const int* dst = ei + N_EDGES;  // edge_index[1]

    float *p_t, *p_h1, *p_sums, *p_cnts;
    int *p_deg, *p_csr;
    cudaGetSymbolAddress((void**)&p_t,    g_t);
    cudaGetSymbolAddress((void**)&p_h1,   g_h1);
    cudaGetSymbolAddress((void**)&p_sums, g_sums);
    cudaGetSymbolAddress((void**)&p_cnts, g_cnts);
    cudaGetSymbolAddress((void**)&p_deg,  g_deg);
    cudaGetSymbolAddress((void**)&p_csr,  g_csr);

    static bool attr_done = false;
    if (!attr_done) {
        cudaFuncSetAttribute(conv_kernel,
                             cudaFuncAttributeMaxDynamicSharedMemorySize,
                             SM_TOTAL);
        attr_done = true;
    }

    const int fill_blocks = (N_EDGES + 255) / 256;          // 3907
    const int gather_blocks = (N_NODES * 16 + 255) / 256;   // 6250
    const int node_blocks = (N_NODES + 255) / 256;          // 391

    // ---- CSR build (shared by both convs) ----
    cudaMemsetAsync(p_deg, 0, (size_t)N_NODES * sizeof(int));
    cudaMemsetAsync(p_sums, 0, (size_t)N_GRAPHS * FEAT * sizeof(float));
    cudaMemsetAsync(p_cnts, 0, (size_t)N_GRAPHS * sizeof(float));
    fill_kernel<<<fill_blocks, 256>>>(src, dst, p_deg, p_csr);
    count_kernel<<<node_blocks, 256>>>(bat, p_cnts);

    // ---- Conv 0 ----
    gather_kernel<<<gather_blocks, 256>>>(x, p_deg, p_csr, p_t);
    conv_kernel<<<GRID_CONV, 256, SM_TOTAL>>>(
        p_t, w0a, b0a, g0, be0, m0, v0,
        w0b, b0b, p_h1, bat, p_sums, /*mode=*/0);

    // ---- Conv 1 (mean-pool sum fused, segmented reduction) ----
    gather_kernel<<<gather_blocks, 256>>>(p_h1, p_deg, p_csr, p_t);
    conv_kernel<<<GRID_CONV, 256, SM_TOTAL>>>(
        p_t, w1a, b1a, g1, be1, m1, v1,
        w1b, b1b, /*out unused*/ p_h1, bat, p_sums, /*mode=*/1);

    // ---- Classify ----
    classify_kernel<<<N_GRAPHS, 64>>>(p_sums, p_cnts, wc, bc, out);
}